// round 1
// baseline (speedup 1.0000x reference)
#include <cuda_runtime.h>
#include <math.h>

// Problem: result = sum_{b,t} w^2 * log(sigmoid(logit)+EPS) * log_probs * (t+1)
//                   / sum(w)
// (reversed-cumsum-then-sum collapses to the (t+1) weighting)
//
// Inputs (metadata order): [0] log_probs f32 [B*T], [1] logits f32 [B*T*1],
//                          [2] weight f32 [B*T].  Output: scalar f32.

#define T_DIM 16384            // inner dim (power of 2)
#define EPS_F 1e-7f
#define NTHREADS 256

__device__ double g_acc[2];    // [0] = term sum, [1] = weight sum

__global__ void zero_acc_kernel() {
    g_acc[0] = 0.0;
    g_acc[1] = 0.0;
}

__device__ __forceinline__ float term_elem(float lp, float lg, float w, float tscale) {
    // rewards = log(sigmoid(lg) + EPS); term = w * (rewards * w) * lp
    float s = 1.0f / (1.0f + expf(-lg));
    float r = logf(s + EPS_F);
    return w * w * r * lp * tscale;
}

__global__ void __launch_bounds__(NTHREADS)
reduce_kernel(const float4* __restrict__ lp,
              const float4* __restrict__ lg,
              const float4* __restrict__ w,
              int n4)
{
    float acc_t = 0.0f;
    float acc_w = 0.0f;

    const int stride = gridDim.x * blockDim.x;
    for (int i = blockIdx.x * blockDim.x + threadIdx.x; i < n4; i += stride) {
        float4 a = lp[i];
        float4 b = lg[i];
        float4 c = w[i];

        // t index of element 0 of this float4 within its row (T_DIM % 4 == 0,
        // so all 4 elements share a row)
        int t0 = (i << 2) & (T_DIM - 1);
        float tw = (float)(t0 + 1);

        acc_t += term_elem(a.x, b.x, c.x, tw);
        acc_t += term_elem(a.y, b.y, c.y, tw + 1.0f);
        acc_t += term_elem(a.z, b.z, c.z, tw + 2.0f);
        acc_t += term_elem(a.w, b.w, c.w, tw + 3.0f);
        acc_w += (c.x + c.y) + (c.z + c.w);
    }

    // warp reduce
    #pragma unroll
    for (int off = 16; off > 0; off >>= 1) {
        acc_t += __shfl_down_sync(0xffffffffu, acc_t, off);
        acc_w += __shfl_down_sync(0xffffffffu, acc_w, off);
    }

    __shared__ float st[NTHREADS / 32];
    __shared__ float sw[NTHREADS / 32];
    const int lane = threadIdx.x & 31;
    const int wid  = threadIdx.x >> 5;
    if (lane == 0) { st[wid] = acc_t; sw[wid] = acc_w; }
    __syncthreads();

    if (wid == 0) {
        acc_t = (lane < NTHREADS / 32) ? st[lane] : 0.0f;
        acc_w = (lane < NTHREADS / 32) ? sw[lane] : 0.0f;
        #pragma unroll
        for (int off = (NTHREADS / 64); off > 0; off >>= 1) {
            acc_t += __shfl_down_sync(0xffffffffu, acc_t, off);
            acc_w += __shfl_down_sync(0xffffffffu, acc_w, off);
        }
        if (lane == 0) {
            atomicAdd(&g_acc[0], (double)acc_t);
            atomicAdd(&g_acc[1], (double)acc_w);
        }
    }
}

__global__ void finalize_kernel(float* out) {
    out[0] = (float)(g_acc[0] / g_acc[1]);
}

extern "C" void kernel_launch(void* const* d_in, const int* in_sizes, int n_in,
                              void* d_out, int out_size) {
    const float4* lp = (const float4*)d_in[0];
    const float4* lg = (const float4*)d_in[1];
    const float4* w  = (const float4*)d_in[2];
    float* out = (float*)d_out;

    const int n  = in_sizes[0];          // B*T elements
    const int n4 = n >> 2;               // float4 count

    // memory-bound streaming reduction: enough blocks to cover all SMs with
    // a few grid-stride iterations each
    int blocks = 148 * 12;
    int max_blocks = (n4 + NTHREADS - 1) / NTHREADS;
    if (blocks > max_blocks) blocks = max_blocks;

    zero_acc_kernel<<<1, 1>>>();
    reduce_kernel<<<blocks, NTHREADS>>>(lp, lg, w, n4);
    finalize_kernel<<<1, 1>>>(out);
}